// round 6
// baseline (speedup 1.0000x reference)
#include <cuda_runtime.h>
#include <math.h>
#include <stdint.h>

#define N_TOK   16384
#define E_DIM   512
#define C_DIM   8
#define K_CODES 8192
#define LN_EPS  1e-5f

// ---------------- scratch (device globals: no allocation allowed) ----------------
__device__ float g_h[N_TOK * E_DIM];        // relu(features@W1_in+b1)   32MB
__device__ float g_z[N_TOK * C_DIM];        // layernormed code-space
__device__ unsigned long long g_key[N_TOK]; // packed (dist,idx) argmin keys
__device__ float g_hq[K_CODES * E_DIM];     // relu(emb@W1_out+b1)       16MB
__device__ float g_tpre[K_CODES * E_DIM];   // pre-LN table              16MB
__device__ float g_tbl[K_CODES * E_DIM];    // final per-code output     16MB

// ================== tf32 split MMA GEMM: C = act(A[Mx512]@B[512x512]+bias) =======
// BM=128, BN=128, BK=16. 8 warps (4x2), warp tile 32m x 64n, mma.m16n8k8.
// A,B fp32 in gmem; split into tf32 hi/lo in SMEM. TERMS=4: hh+hl+lh+ll
// (error ~2^-24, fp32-noise level, safe for the argmin path). TERMS=3: drops ll.
#define ASTR 20    // A smem row stride (floats) — conflict-free fragment loads
#define BSTR 136   // B smem row stride (floats)

__device__ __forceinline__ uint32_t f2tf32(float x) {
    uint32_t u;
    asm("cvt.rna.tf32.f32 %0, %1;" : "=r"(u) : "f"(x));
    return u;
}

#define MMA_TF32(d, a, b) \
    asm volatile("mma.sync.aligned.m16n8k8.row.col.f32.tf32.tf32.f32 " \
        "{%0,%1,%2,%3},{%4,%5,%6,%7},{%8,%9},{%0,%1,%2,%3};" \
        : "+f"(d[0]),"+f"(d[1]),"+f"(d[2]),"+f"(d[3]) \
        : "r"(a[0]),"r"(a[1]),"r"(a[2]),"r"(a[3]),"r"(b[0]),"r"(b[1]))

template <int DO_RELU, int TERMS>
__global__ __launch_bounds__(256) void mma_gemm(
    const float* __restrict__ A, const float* __restrict__ B,
    const float* __restrict__ bias, float* __restrict__ C)
{
    __shared__ float sAh[128 * ASTR];
    __shared__ float sAl[128 * ASTR];
    __shared__ float sBh[16 * BSTR];
    __shared__ float sBl[16 * BSTR];

    int tid = threadIdx.x, lane = tid & 31, warp = tid >> 5;
    int wm = warp >> 1, wn = warp & 1;
    int crow = blockIdx.y * 128, ccol = blockIdx.x * 128;

    float acc[2][8][4];
#pragma unroll
    for (int mt = 0; mt < 2; mt++)
#pragma unroll
        for (int nt = 0; nt < 8; nt++)
#pragma unroll
            for (int r = 0; r < 4; r++) acc[mt][nt][r] = 0.f;

    for (int kt = 0; kt < 32; kt++) {
        int k0 = kt * 16;
        if (kt) __syncthreads();
        // A tile: 128 rows x 16 cols = 512 float4
#pragma unroll
        for (int u = 0; u < 2; u++) {
            int idx = tid + u * 256;
            int r = idx >> 2, c4 = (idx & 3) * 4;
            float4 v = *(const float4*)(A + (size_t)(crow + r) * 512 + k0 + c4);
            float vv[4] = {v.x, v.y, v.z, v.w};
#pragma unroll
            for (int j = 0; j < 4; j++) {
                float hi = __uint_as_float(f2tf32(vv[j]));
                sAh[r * ASTR + c4 + j] = hi;
                sAl[r * ASTR + c4 + j] = __uint_as_float(f2tf32(vv[j] - hi));
            }
        }
        // B tile: 16 rows x 128 cols = 512 float4
#pragma unroll
        for (int u = 0; u < 2; u++) {
            int idx = tid + u * 256;
            int r = idx >> 5, c4 = (idx & 31) * 4;
            float4 v = *(const float4*)(B + (size_t)(k0 + r) * 512 + ccol + c4);
            float vv[4] = {v.x, v.y, v.z, v.w};
#pragma unroll
            for (int j = 0; j < 4; j++) {
                float hi = __uint_as_float(f2tf32(vv[j]));
                sBh[r * BSTR + c4 + j] = hi;
                sBl[r * BSTR + c4 + j] = __uint_as_float(f2tf32(vv[j] - hi));
            }
        }
        __syncthreads();

#pragma unroll
        for (int kk = 0; kk < 16; kk += 8) {
            uint32_t ah[2][4], al[2][4];
#pragma unroll
            for (int mt = 0; mt < 2; mt++) {
                int r0 = wm * 32 + mt * 16 + (lane >> 2);
                int c0 = kk + (lane & 3);
                ah[mt][0] = __float_as_uint(sAh[r0 * ASTR + c0]);
                ah[mt][1] = __float_as_uint(sAh[(r0 + 8) * ASTR + c0]);
                ah[mt][2] = __float_as_uint(sAh[r0 * ASTR + c0 + 4]);
                ah[mt][3] = __float_as_uint(sAh[(r0 + 8) * ASTR + c0 + 4]);
                al[mt][0] = __float_as_uint(sAl[r0 * ASTR + c0]);
                al[mt][1] = __float_as_uint(sAl[(r0 + 8) * ASTR + c0]);
                al[mt][2] = __float_as_uint(sAl[r0 * ASTR + c0 + 4]);
                al[mt][3] = __float_as_uint(sAl[(r0 + 8) * ASTR + c0 + 4]);
            }
            uint32_t bh[8][2], bl[8][2];
#pragma unroll
            for (int nt = 0; nt < 8; nt++) {
                int col = wn * 64 + nt * 8 + (lane >> 2);
                int kr  = kk + (lane & 3);
                bh[nt][0] = __float_as_uint(sBh[kr * BSTR + col]);
                bh[nt][1] = __float_as_uint(sBh[(kr + 4) * BSTR + col]);
                bl[nt][0] = __float_as_uint(sBl[kr * BSTR + col]);
                bl[nt][1] = __float_as_uint(sBl[(kr + 4) * BSTR + col]);
            }
#pragma unroll
            for (int mt = 0; mt < 2; mt++)
#pragma unroll
                for (int nt = 0; nt < 8; nt++) {
                    MMA_TF32(acc[mt][nt], ah[mt], bh[nt]);
                    MMA_TF32(acc[mt][nt], ah[mt], bl[nt]);
                    MMA_TF32(acc[mt][nt], al[mt], bh[nt]);
                    if (TERMS == 4)
                        MMA_TF32(acc[mt][nt], al[mt], bl[nt]);
                }
        }
    }

    // epilogue: d0,d1 at (r, c..c+1); d2,d3 at (r+8, c..c+1)
#pragma unroll
    for (int mt = 0; mt < 2; mt++)
#pragma unroll
        for (int nt = 0; nt < 8; nt++) {
            int r = crow + wm * 32 + mt * 16 + (lane >> 2);
            int c = ccol + wn * 64 + nt * 8 + (lane & 3) * 2;
            float b0 = bias[c], b1 = bias[c + 1];
            float o0 = acc[mt][nt][0] + b0;
            float o1 = acc[mt][nt][1] + b1;
            float o2 = acc[mt][nt][2] + b0;
            float o3 = acc[mt][nt][3] + b1;
            if (DO_RELU) {
                o0 = fmaxf(o0, 0.f); o1 = fmaxf(o1, 0.f);
                o2 = fmaxf(o2, 0.f); o3 = fmaxf(o3, 0.f);
            }
            float2 w0 = make_float2(o0, o1);
            float2 w1 = make_float2(o2, o3);
            *(float2*)(C + (size_t)r * 512 + c)       = w0;
            *(float2*)(C + (size_t)(r + 8) * 512 + c) = w1;
        }
}

// ---------------- z = LN(h @ W2_in + b2)  — one warp per token ----------------
__global__ __launch_bounds__(256) void gemm2_ln(
    const float* __restrict__ h, const float* __restrict__ W2,
    const float* __restrict__ b2, const float* __restrict__ g,
    const float* __restrict__ b, float* __restrict__ z)
{
    __shared__ float w2t[C_DIM * E_DIM];
    int tid = threadIdx.x;
    for (int i = tid; i < C_DIM * E_DIM; i += 256) {
        int c = i >> 9, e = i & 511;
        w2t[i] = W2[e * C_DIM + c];
    }
    __syncthreads();

    int warp = tid >> 5, lane = tid & 31;
    int tok = blockIdx.x * 8 + warp;
    const float* hr = h + (size_t)tok * E_DIM;

    float acc[8] = {0.f, 0.f, 0.f, 0.f, 0.f, 0.f, 0.f, 0.f};
#pragma unroll
    for (int i = 0; i < 16; i++) {
        int e = i * 32 + lane;
        float hv = hr[e];
#pragma unroll
        for (int c = 0; c < 8; c++)
            acc[c] = fmaf(hv, w2t[c * 512 + e], acc[c]);
    }
#pragma unroll
    for (int c = 0; c < 8; c++)
#pragma unroll
        for (int off = 16; off > 0; off >>= 1)
            acc[c] += __shfl_xor_sync(0xffffffffu, acc[c], off);

    float zc[8], mu = 0.f;
#pragma unroll
    for (int c = 0; c < 8; c++) { zc[c] = acc[c] + b2[c]; mu += zc[c]; }
    mu *= 0.125f;
    float var = 0.f;
#pragma unroll
    for (int c = 0; c < 8; c++) { float d = zc[c] - mu; var = fmaf(d, d, var); }
    var *= 0.125f;
    float rinv = 1.0f / sqrtf(var + LN_EPS);

    if (lane == 0) {
        float o[8];
#pragma unroll
        for (int c = 0; c < 8; c++) o[c] = (zc[c] - mu) * rinv * g[c] + b[c];
        *(float4*)(z + (size_t)tok * 8)     = make_float4(o[0], o[1], o[2], o[3]);
        *(float4*)(z + (size_t)tok * 8 + 4) = make_float4(o[4], o[5], o[6], o[7]);
    }
}

// ---------------- argmin over codebook (broadcast-LDS, register tokens) ----------
#define CHUNK 512
__global__ __launch_bounds__(256) void argmin_kernel(
    const float* __restrict__ emb, const float* __restrict__ z)
{
    __shared__ float se[CHUNK * 8];
    __shared__ float ss[CHUNK];

    int tid  = threadIdx.x;
    int warp = tid >> 5, lane = tid & 31;
    int c0   = blockIdx.x * CHUNK;
    int tok0 = blockIdx.y * 1024 + warp * 128 + lane * 4;

    const float4* src = (const float4*)(emb + (size_t)c0 * 8);
#pragma unroll
    for (int u = 0; u < 4; u++) ((float4*)se)[tid + 256 * u] = src[tid + 256 * u];
    __syncthreads();
#pragma unroll
    for (int u = 0; u < 2; u++) {
        int c = tid + 256 * u;
        const float* e = se + c * 8;
        float s = e[0] * e[0];
#pragma unroll
        for (int j = 1; j < 8; j++) s = fmaf(e[j], e[j], s);
        ss[c] = s;
    }
    __syncthreads();

    float zr[4][8], sz2[4];
#pragma unroll
    for (int t = 0; t < 4; t++) {
        float4 a = *(const float4*)(z + (size_t)(tok0 + t) * 8);
        float4 b = *(const float4*)(z + (size_t)(tok0 + t) * 8 + 4);
        zr[t][0] = a.x; zr[t][1] = a.y; zr[t][2] = a.z; zr[t][3] = a.w;
        zr[t][4] = b.x; zr[t][5] = b.y; zr[t][6] = b.z; zr[t][7] = b.w;
        float s = a.x * a.x;
        s = fmaf(a.y, a.y, s); s = fmaf(a.z, a.z, s); s = fmaf(a.w, a.w, s);
        s = fmaf(b.x, b.x, s); s = fmaf(b.y, b.y, s);
        s = fmaf(b.z, b.z, s); s = fmaf(b.w, b.w, s);
        sz2[t] = s;
    }

    float bestd[4];
    int   besti[4];
#pragma unroll
    for (int t = 0; t < 4; t++) { bestd[t] = __int_as_float(0x7f800000); besti[t] = 0; }

#pragma unroll 2
    for (int c = 0; c < CHUNK; c++) {
        float4 ea = *(const float4*)(se + c * 8);
        float4 eb = *(const float4*)(se + c * 8 + 4);
        float ssc = ss[c];
#pragma unroll
        for (int t = 0; t < 4; t++) {
            float dot = zr[t][0] * ea.x;
            dot = fmaf(zr[t][1], ea.y, dot);
            dot = fmaf(zr[t][2], ea.z, dot);
            dot = fmaf(zr[t][3], ea.w, dot);
            dot = fmaf(zr[t][4], eb.x, dot);
            dot = fmaf(zr[t][5], eb.y, dot);
            dot = fmaf(zr[t][6], eb.z, dot);
            dot = fmaf(zr[t][7], eb.w, dot);
            float d = (sz2[t] - 2.0f * dot) + ssc;
            if (d < bestd[t]) { bestd[t] = d; besti[t] = c0 + c; }
        }
    }

#pragma unroll
    for (int t = 0; t < 4; t++) {
        unsigned int m = __float_as_uint(bestd[t]);
        m = ((int)m < 0) ? ~m : (m | 0x80000000u);
        unsigned long long key = ((unsigned long long)m << 32) | (unsigned)besti[t];
        atomicMin(&g_key[tok0 + t], key);
    }
}

// ---------------- hq = relu(emb @ W1_out + b1_out)  (8192 x 512) ----------------
__global__ void proj_out1(const float* __restrict__ emb,
                          const float* __restrict__ W1o,
                          const float* __restrict__ b1o)
{
    int i = blockIdx.x * 256 + threadIdx.x;
    int k = i >> 9, e = i & 511;
    const float* er = emb + (size_t)k * 8;
    float acc = er[0] * W1o[e];
#pragma unroll
    for (int c = 1; c < 8; c++) acc = fmaf(er[c], W1o[c * 512 + e], acc);
    acc += b1o[e];
    g_hq[i] = fmaxf(acc, 0.f);
}

// ---------------- row LayerNorm over E=512 — one warp per row ----------------
__global__ __launch_bounds__(256) void ln_rows(
    const float* __restrict__ x, const float* __restrict__ g,
    const float* __restrict__ b, float* __restrict__ y)
{
    int warp = (blockIdx.x * 256 + threadIdx.x) >> 5;
    int lane = threadIdx.x & 31;
    const float* r = x + (size_t)warp * 512;

    float4 v[4];
    float s = 0.f;
#pragma unroll
    for (int i = 0; i < 4; i++) {
        v[i] = ((const float4*)r)[lane + 32 * i];
        s += v[i].x + v[i].y + v[i].z + v[i].w;
    }
#pragma unroll
    for (int off = 16; off > 0; off >>= 1) s += __shfl_xor_sync(0xffffffffu, s, off);
    float mu = s * (1.0f / 512.0f);

    float s2 = 0.f;
#pragma unroll
    for (int i = 0; i < 4; i++) {
        float dx;
        dx = v[i].x - mu; s2 = fmaf(dx, dx, s2);
        dx = v[i].y - mu; s2 = fmaf(dx, dx, s2);
        dx = v[i].z - mu; s2 = fmaf(dx, dx, s2);
        dx = v[i].w - mu; s2 = fmaf(dx, dx, s2);
    }
#pragma unroll
    for (int off = 16; off > 0; off >>= 1) s2 += __shfl_xor_sync(0xffffffffu, s2, off);
    float var = s2 * (1.0f / 512.0f);
    float inv = 1.0f / sqrtf(var + LN_EPS);

#pragma unroll
    for (int i = 0; i < 4; i++) {
        int e = 4 * (lane + 32 * i);
        float4 gg = *(const float4*)(g + e);
        float4 bb = *(const float4*)(b + e);
        float4 o;
        o.x = (v[i].x - mu) * inv * gg.x + bb.x;
        o.y = (v[i].y - mu) * inv * gg.y + bb.y;
        o.z = (v[i].z - mu) * inv * gg.z + bb.z;
        o.w = (v[i].w - mu) * inv * gg.w + bb.w;
        ((float4*)(y + (size_t)warp * 512))[lane + 32 * i] = o;
    }
}

// ---------------- gather: q rows, idx (as float), one-hot scatter ----------------
__global__ void gather_out(float* __restrict__ outq, float* __restrict__ outidx,
                           float* __restrict__ outenc)
{
    int tok = blockIdx.x;
    int k = (int)(g_key[tok] & 0xFFFFFFFFull);
    int t = threadIdx.x;
    float4 v = ((const float4*)(g_tbl + (size_t)k * 512))[t];
    ((float4*)(outq + (size_t)tok * 512))[t] = v;
    if (t == 0) {
        if (outidx) outidx[tok] = (float)k;
        if (outenc) outenc[(size_t)tok * K_CODES + k] = 1.0f;
    }
}

// ---------------- launch ----------------
extern "C" void kernel_launch(void* const* d_in, const int* in_sizes, int n_in,
                              void* d_out, int out_size)
{
    const float* features = (const float*)d_in[0];
    const float* W1_in    = (const float*)d_in[1];
    const float* b1_in    = (const float*)d_in[2];
    const float* W2_in    = (const float*)d_in[3];
    const float* b2_in    = (const float*)d_in[4];
    const float* ln_in_g  = (const float*)d_in[5];
    const float* ln_in_b  = (const float*)d_in[6];
    const float* emb      = (const float*)d_in[7];
    const float* W1_out   = (const float*)d_in[8];
    const float* b1_out   = (const float*)d_in[9];
    const float* W2_out   = (const float*)d_in[10];
    const float* b2_out   = (const float*)d_in[11];
    const float* ln_out_g = (const float*)d_in[12];
    const float* ln_out_b = (const float*)d_in[13];

    float* out = (float*)d_out;
    const long long q_elems   = (long long)N_TOK * E_DIM;
    const long long idx_elems = N_TOK;
    const long long enc_elems = (long long)N_TOK * K_CODES;
    float* outq   = out;
    float* outidx = nullptr;
    float* outenc = nullptr;
    if ((long long)out_size >= q_elems + idx_elems + enc_elems) {
        outidx = out + q_elems;
        outenc = out + q_elems + idx_elems;
    } else if ((long long)out_size >= q_elems + idx_elems) {
        outidx = out + q_elems;
    }

    float *p_h, *p_z, *p_hq, *p_tpre, *p_tbl;
    void* p_key;
    cudaGetSymbolAddress((void**)&p_h,    g_h);
    cudaGetSymbolAddress((void**)&p_z,    g_z);
    cudaGetSymbolAddress((void**)&p_hq,   g_hq);
    cudaGetSymbolAddress((void**)&p_tpre, g_tpre);
    cudaGetSymbolAddress((void**)&p_tbl,  g_tbl);
    cudaGetSymbolAddress(&p_key, g_key);

    // side stream for the DRAM-bound encodings memset only
    static cudaStream_t sC = nullptr;
    static cudaEvent_t evF = nullptr, evC = nullptr;
    if (!sC) {
        cudaStreamCreateWithFlags(&sC, cudaStreamNonBlocking);
        cudaEventCreateWithFlags(&evF, cudaEventDisableTiming);
        cudaEventCreateWithFlags(&evC, cudaEventDisableTiming);
    }

    cudaEventRecord(evF, 0);
    cudaStreamWaitEvent(sC, evF, 0);
    if (outenc)
        cudaMemsetAsync(outenc, 0, (size_t)enc_elems * sizeof(float), sC);
    cudaEventRecord(evC, sC);

    // ---- stream 0: all compute ----
    cudaMemsetAsync(p_key, 0xFF, N_TOK * sizeof(unsigned long long), 0);

    // GEMM1: tf32 4-term split (argmin-critical; fp32-noise-level accuracy)
    mma_gemm<1, 4><<<dim3(4, N_TOK / 128), 256>>>(features, W1_in, b1_in, p_h);
    gemm2_ln<<<N_TOK / 8, 256>>>(p_h, W2_in, b2_in, ln_in_g, ln_in_b, p_z);
    argmin_kernel<<<dim3(K_CODES / CHUNK, N_TOK / 1024), 256>>>(emb, p_z);

    proj_out1<<<(K_CODES * E_DIM) / 256, 256>>>(emb, W1_out, b1_out);
    // table GEMM: tf32 3-term split (output-only accuracy, ~4e-6)
    mma_gemm<0, 3><<<dim3(4, K_CODES / 128), 256>>>(p_hq, W2_out, b2_out, p_tpre);
    ln_rows<<<K_CODES / 8, 256>>>(p_tpre, ln_out_g, ln_out_b, p_tbl);

    // join + final gather
    cudaStreamWaitEvent(0, evC, 0);
    gather_out<<<N_TOK, 128>>>(outq, outidx, outenc);
}